// round 14
// baseline (speedup 1.0000x reference)
#include <cuda_runtime.h>
#include <cstdint>

#define N_NODES 50000
#define N_USERC 40000
#define NE      400000
#define KK      3
#define NH      4
#define F_INC   128
#define F_OUTC  64
#define NC      40
#define SLOPE   0.2f
#define CAP     64

// ---------------- scratch (device globals; no allocations) ----------------
// hp layout: [k][n][f][h]  (head-minor so 4 heads load as one float4)
__device__ float g_hp [(size_t)KK * N_NODES * 256];   // 153.6 MB
__device__ float g_s  [KK * N_NODES * 4];
__device__ float g_t  [KK * N_NODES * 4];
__device__ float g_x  [KK * N_USERC * 64];
__device__ int   g_cnt[KK * N_USERC];
__device__ int   g_adj[(size_t)KK * N_USERC * CAP];
// B weights pre-arranged in m16n8k8 tf32 fragment order:
// g_bfrag[k][ ((ch*16+ks)*16+nt)*32 + lane ] = { B[ks*8+lane%4][c], B[ks*8+lane%4+4][c] }
// where c = ch*128 + nt*8 + lane/4 and B[d][c] = w[k][c&3][d][c>>2]   (tf32 bits)
__device__ uint2 g_bfrag[KK * 16384];                 // 384 KB

__device__ __forceinline__ uint32_t f2tf32(float f) {
    uint32_t r;
    asm("cvt.rna.tf32.f32 %0, %1;" : "=r"(r) : "f"(f));
    return r;
}

__device__ __forceinline__ void mma_tf32(float* d, const uint32_t* a, uint2 b) {
    asm volatile(
        "mma.sync.aligned.m16n8k8.row.col.f32.tf32.tf32.f32 "
        "{%0,%1,%2,%3}, {%4,%5,%6,%7}, {%8,%9}, {%0,%1,%2,%3};\n"
        : "+f"(d[0]), "+f"(d[1]), "+f"(d[2]), "+f"(d[3])
        : "r"(a[0]), "r"(a[1]), "r"(a[2]), "r"(a[3]), "r"(b.x), "r"(b.y));
}

// ---------------- zero degree counters ----------------
__global__ void k_zero() {
    int i = blockIdx.x * blockDim.x + threadIdx.x;
    if (i < KK * N_USERC) g_cnt[i] = 0;
}

// ---------------- build per-target adjacency buckets ----------------
__global__ void k_fill(const int* __restrict__ ei) {
    int idx = blockIdx.x * blockDim.x + threadIdx.x;
    if (idx >= KK * NE) return;
    int k = idx / NE;
    int e = idx - k * NE;
    int trg = ei[(k * 2 + 1) * NE + e];
    if (trg >= N_USERC) return;
    int src = ei[(k * 2) * NE + e];
    int slot = k * N_USERC + trg;
    int pos = atomicAdd(&g_cnt[slot], 1);
    if (pos < CAP) g_adj[(size_t)slot * CAP + pos] = src;
}

// ---------------- pre-arrange B into fragment order (runs once, tiny) ----------------
__global__ void k_prepB(const float* __restrict__ w) {
    int id = blockIdx.x * blockDim.x + threadIdx.x;
    if (id >= KK * 16384) return;
    int kk   = id / 16384;
    int r    = id - kk * 16384;
    int lane = r & 31;
    int nt   = (r >> 5) & 15;
    int ks   = (r >> 9) & 15;
    int ch   = r >> 13;
    int d0   = ks * 8 + (lane & 3);
    int c    = ch * 128 + nt * 8 + (lane >> 2);
    int f    = c >> 2, hh = c & 3;
    const float* wk = w + (size_t)kk * NH * F_INC * F_OUTC;
    uint2 b;
    b.x = f2tf32(wk[((size_t)hh * F_INC + d0) * F_OUTC + f]);
    b.y = f2tf32(wk[((size_t)hh * F_INC + d0 + 4) * F_OUTC + f]);
    g_bfrag[id] = b;
}

// ================= tensor-core tf32 GEMM: hp = h @ w[k] + fused s,t =================
// CTA: 64 rows x 256 cols x K=128. 8 warps = 4 row-tiles x 2 col-halves.
// Each warp: 16 k-steps x 16 n-tiles of m16n8k8.
#define A_PAD   132                      // 128 + 4 floats, bank-conflict-free frags
#define A_BYTES (64 * A_PAD * 4)         // 33792
#define B_BYTES (16384 * 8)              // 131072
#define SMEM_DYN (A_BYTES + B_BYTES + 6144)

__global__ __launch_bounds__(256, 1)
void k_gemm(const float* __restrict__ h, const float* __restrict__ a_src,
            const float* __restrict__ a_trg) {
    extern __shared__ __align__(16) char base[];
    float* Asm    = (float*)base;
    uint2* Bsm    = (uint2*)(base + A_BYTES);
    float* s_asr  = (float*)(base + A_BYTES + B_BYTES);          // 256
    float* s_atr  = s_asr + 256;                                 // 256
    float* sred_s = s_atr + 256;                                 // 512
    float* sred_t = sred_s + 512;                                // 512

    const int k    = blockIdx.y;
    const int n0   = blockIdx.x * 64;
    const int tid  = threadIdx.x;
    const int wid  = tid >> 5;
    const int lane = tid & 31;
    const int rt   = wid & 3;       // row tile
    const int ch   = wid >> 2;      // col half
    const int g    = lane >> 2;     // group (row within tile)
    const int c    = lane & 3;      // thread-in-group

    // reordered attention coefficient tables: [c] = a[k][c&3][c>>2]
    if (tid < 256) {
        s_asr[tid] = a_src[k * 256 + (tid & 3) * 64 + (tid >> 2)];
        s_atr[tid] = a_trg[k * 256 + (tid & 3) * 64 + (tid >> 2)];
    }

    // stage A (64x128 fp32 -> tf32, padded rows)
    for (int idx = tid; idx < 64 * 32; idx += 256) {
        int row = idx >> 5;
        int c4  = idx & 31;
        int n   = n0 + row;
        float4 av = make_float4(0.f, 0.f, 0.f, 0.f);
        if (n < N_NODES) av = *(const float4*)(h + (size_t)n * F_INC + c4 * 4);
        uint4 tv;
        tv.x = f2tf32(av.x); tv.y = f2tf32(av.y); tv.z = f2tf32(av.z); tv.w = f2tf32(av.w);
        *(uint4*)(Asm + row * A_PAD + c4 * 4) = tv;
    }
    // copy pre-arranged B fragments (coalesced)
    {
        const uint4* src = (const uint4*)(g_bfrag + (size_t)k * 16384);
        uint4* dst = (uint4*)Bsm;
        for (int idx = tid; idx < 8192; idx += 256) dst[idx] = src[idx];
    }
    __syncthreads();

    float acc[16][4];
#pragma unroll
    for (int nt = 0; nt < 16; nt++)
#pragma unroll
        for (int j = 0; j < 4; j++) acc[nt][j] = 0.f;

    const float* arow = Asm + (rt * 16 + g) * A_PAD;
#pragma unroll 4
    for (int ks = 0; ks < 16; ks++) {
        int col = ks * 8 + c;
        uint32_t a[4];
        a[0] = __float_as_uint(arow[col]);
        a[1] = __float_as_uint(arow[8 * A_PAD + col]);
        a[2] = __float_as_uint(arow[col + 4]);
        a[3] = __float_as_uint(arow[8 * A_PAD + col + 4]);
        const uint2* bk = Bsm + ((ch * 16 + ks) * 16) * 32 + lane;
#pragma unroll
        for (int nt = 0; nt < 16; nt++)
            mma_tf32(acc[nt], a, bk[nt * 32]);
    }

    // epilogue: hp stores + per-thread s/t partials
    int nrow0 = n0 + rt * 16 + g;
    int nrow1 = nrow0 + 8;
    float sp00 = 0.f, sp01 = 0.f, sp10 = 0.f, sp11 = 0.f;
    float tp00 = 0.f, tp01 = 0.f, tp10 = 0.f, tp11 = 0.f;
    float* hp0 = g_hp + ((size_t)k * N_NODES + nrow0) * 256;
    float* hp1 = g_hp + ((size_t)k * N_NODES + nrow1) * 256;
    bool ok0 = (nrow0 < N_NODES), ok1 = (nrow1 < N_NODES);
#pragma unroll
    for (int nt = 0; nt < 16; nt++) {
        int cb = ch * 128 + nt * 8 + 2 * c;
        float w0 = s_asr[cb], w1 = s_asr[cb + 1];
        float v0 = s_atr[cb], v1 = s_atr[cb + 1];
        sp00 += acc[nt][0] * w0; sp01 += acc[nt][1] * w1;
        sp10 += acc[nt][2] * w0; sp11 += acc[nt][3] * w1;
        tp00 += acc[nt][0] * v0; tp01 += acc[nt][1] * v1;
        tp10 += acc[nt][2] * v0; tp11 += acc[nt][3] * v1;
        if (ok0) *(float2*)(hp0 + cb) = make_float2(acc[nt][0], acc[nt][1]);
        if (ok1) *(float2*)(hp1 + cb) = make_float2(acc[nt][2], acc[nt][3]);
    }
    // quad-reduce: lane c combines with c^2 (same head pair)
    sp00 += __shfl_xor_sync(0xffffffffu, sp00, 2);
    sp01 += __shfl_xor_sync(0xffffffffu, sp01, 2);
    sp10 += __shfl_xor_sync(0xffffffffu, sp10, 2);
    sp11 += __shfl_xor_sync(0xffffffffu, sp11, 2);
    tp00 += __shfl_xor_sync(0xffffffffu, tp00, 2);
    tp01 += __shfl_xor_sync(0xffffffffu, tp01, 2);
    tp10 += __shfl_xor_sync(0xffffffffu, tp10, 2);
    tp11 += __shfl_xor_sync(0xffffffffu, tp11, 2);
    if (c < 2) {
        int b0 = ((wid * 8 + g) * 2 + 0) * 4 + 2 * c;
        int b1 = ((wid * 8 + g) * 2 + 1) * 4 + 2 * c;
        sred_s[b0] = sp00; sred_s[b0 + 1] = sp01;
        sred_s[b1] = sp10; sred_s[b1 + 1] = sp11;
        sred_t[b0] = tp00; sred_t[b0 + 1] = tp01;
        sred_t[b1] = tp10; sred_t[b1 + 1] = tp11;
    }
    __syncthreads();
    // final cross-colhalf combine: tid -> (row, head)
    {
        int row = tid >> 2, hh = tid & 3;
        int n = n0 + row;
        if (n < N_NODES) {
            int rtf = row >> 4, rr = row & 15, gg = rr & 7, r = rr >> 3;
            int i0 = ((rtf * 8 + gg) * 2 + r) * 4 + hh;
            int i1 = (((rtf + 4) * 8 + gg) * 2 + r) * 4 + hh;
            size_t o = ((size_t)k * N_NODES + n) * 4 + hh;
            g_s[o] = sred_s[i0] + sred_s[i1];
            g_t[o] = sred_t[i0] + sred_t[i1];
        }
    }
}

__device__ __forceinline__ float lrelu_exp(float v) {
    v = (v >= 0.f) ? v : SLOPE * v;
    return __expf(v);
}

// ---------------- fused softmax + aggregation (warp per (k,trg)) ----------------
__global__ __launch_bounds__(256) void k_agg() {
    int gw   = (blockIdx.x * blockDim.x + threadIdx.x) >> 5;
    int lane = threadIdx.x & 31;
    if (gw >= KK * N_USERC) return;
    int k = gw / N_USERC;
    int n = gw - k * N_USERC;
    float* xr = g_x + (size_t)gw * 64;

    int deg = g_cnt[gw];
    deg = (deg > CAP) ? CAP : deg;
    if (deg == 0) {
        xr[lane] = 0.f;
        xr[lane + 32] = 0.f;
        return;
    }
    float4 tv = *(const float4*)(g_t + ((size_t)k * N_NODES + n) * 4);
    const int* adj = g_adj + (size_t)gw * CAP;

    int src0 = (lane < deg)      ? adj[lane]      : 0;
    int src1 = (lane + 32 < deg) ? adj[lane + 32] : 0;
    float4 ex0 = make_float4(0.f, 0.f, 0.f, 0.f);
    float4 ex1 = make_float4(0.f, 0.f, 0.f, 0.f);
    if (lane < deg) {
        float4 sv = *(const float4*)(g_s + ((size_t)k * N_NODES + src0) * 4);
        ex0.x = lrelu_exp(sv.x + tv.x); ex0.y = lrelu_exp(sv.y + tv.y);
        ex0.z = lrelu_exp(sv.z + tv.z); ex0.w = lrelu_exp(sv.w + tv.w);
    }
    if (lane + 32 < deg) {
        float4 sv = *(const float4*)(g_s + ((size_t)k * N_NODES + src1) * 4);
        ex1.x = lrelu_exp(sv.x + tv.x); ex1.y = lrelu_exp(sv.y + tv.y);
        ex1.z = lrelu_exp(sv.z + tv.z); ex1.w = lrelu_exp(sv.w + tv.w);
    }
    float dx = ex0.x + ex1.x, dy = ex0.y + ex1.y, dz = ex0.z + ex1.z, dw = ex0.w + ex1.w;
#pragma unroll
    for (int off = 16; off; off >>= 1) {
        dx += __shfl_xor_sync(0xffffffffu, dx, off);
        dy += __shfl_xor_sync(0xffffffffu, dy, off);
        dz += __shfl_xor_sync(0xffffffffu, dz, off);
        dw += __shfl_xor_sync(0xffffffffu, dw, off);
    }
    // pre-scale exp values by 1/(4*denom) so the gather loop is pure FMA
    float ix = 0.25f / (dx + 1e-16f);
    float iy = 0.25f / (dy + 1e-16f);
    float iz = 0.25f / (dz + 1e-16f);
    float iw = 0.25f / (dw + 1e-16f);
    ex0.x *= ix; ex0.y *= iy; ex0.z *= iz; ex0.w *= iw;
    ex1.x *= ix; ex1.y *= iy; ex1.z *= iz; ex1.w *= iw;

    const float4* hpb = ((const float4*)g_hp) + (size_t)k * N_NODES * 64;
    float m0 = 0.f, m1 = 0.f;
    int d0 = (deg < 32) ? deg : 32;
    int j = 0;
    // 4-way unrolled gather: 8 LDG.128 in flight per step
    for (; j + 4 <= d0; j += 4) {
        int s0 = __shfl_sync(0xffffffffu, src0, j);
        int s1 = __shfl_sync(0xffffffffu, src0, j + 1);
        int s2 = __shfl_sync(0xffffffffu, src0, j + 2);
        int s3 = __shfl_sync(0xffffffffu, src0, j + 3);
        float ax0 = __shfl_sync(0xffffffffu, ex0.x, j);
        float ay0 = __shfl_sync(0xffffffffu, ex0.y, j);
        float az0 = __shfl_sync(0xffffffffu, ex0.z, j);
        float aw0 = __shfl_sync(0xffffffffu, ex0.w, j);
        float ax1 = __shfl_sync(0xffffffffu, ex0.x, j + 1);
        float ay1 = __shfl_sync(0xffffffffu, ex0.y, j + 1);
        float az1 = __shfl_sync(0xffffffffu, ex0.z, j + 1);
        float aw1 = __shfl_sync(0xffffffffu, ex0.w, j + 1);
        float ax2 = __shfl_sync(0xffffffffu, ex0.x, j + 2);
        float ay2 = __shfl_sync(0xffffffffu, ex0.y, j + 2);
        float az2 = __shfl_sync(0xffffffffu, ex0.z, j + 2);
        float aw2 = __shfl_sync(0xffffffffu, ex0.w, j + 2);
        float ax3 = __shfl_sync(0xffffffffu, ex0.x, j + 3);
        float ay3 = __shfl_sync(0xffffffffu, ex0.y, j + 3);
        float az3 = __shfl_sync(0xffffffffu, ex0.z, j + 3);
        float aw3 = __shfl_sync(0xffffffffu, ex0.w, j + 3);
        const float4* p0 = hpb + (size_t)s0 * 64;
        const float4* p1 = hpb + (size_t)s1 * 64;
        const float4* p2 = hpb + (size_t)s2 * 64;
        const float4* p3 = hpb + (size_t)s3 * 64;
        float4 u0 = p0[lane], w0 = p0[lane + 32];
        float4 u1 = p1[lane], w1 = p1[lane + 32];
        float4 u2 = p2[lane], w2 = p2[lane + 32];
        float4 u3 = p3[lane], w3 = p3[lane + 32];
        m0 += u0.x * ax0 + u0.y * ay0 + u0.z * az0 + u0.w * aw0;
        m1 += w0.x * ax0 + w0.y * ay0 + w0.z * az0 + w0.w * aw0;
        m0 += u1.x * ax1 + u1.y * ay1 + u1.z * az1 + u1.w * aw1;
        m1 += w1.x * ax1 + w1.y * ay1 + w1.z * az1 + w1.w * aw1;
        m0 += u2.x * ax2 + u2.y * ay2 + u2.z * az2 + u2.w * aw2;
        m1 += w2.x * ax2 + w2.y * ay2 + w2.z * az2 + w2.w * aw2;
        m0 += u3.x * ax3 + u3.y * ay3 + u3.z * az3 + u3.w * aw3;
        m1 += w3.x * ax3 + w3.y * ay3 + w3.z * az3 + w3.w * aw3;
    }
    for (; j < d0; j++) {
        int   s  = __shfl_sync(0xffffffffu, src0, j);
        float ax = __shfl_sync(0xffffffffu, ex0.x, j);
        float ay = __shfl_sync(0xffffffffu, ex0.y, j);
        float az = __shfl_sync(0xffffffffu, ex0.z, j);
        float aw = __shfl_sync(0xffffffffu, ex0.w, j);
        const float4* hp4 = hpb + (size_t)s * 64;
        float4 h0 = hp4[lane];
        float4 h1 = hp4[lane + 32];
        m0 += h0.x * ax + h0.y * ay + h0.z * az + h0.w * aw;
        m1 += h1.x * ax + h1.y * ay + h1.z * az + h1.w * aw;
    }
    for (j = 32; j < deg; j++) {
        int   s  = __shfl_sync(0xffffffffu, src1, j - 32);
        float ax = __shfl_sync(0xffffffffu, ex1.x, j - 32);
        float ay = __shfl_sync(0xffffffffu, ex1.y, j - 32);
        float az = __shfl_sync(0xffffffffu, ex1.z, j - 32);
        float aw = __shfl_sync(0xffffffffu, ex1.w, j - 32);
        const float4* hp4 = hpb + (size_t)s * 64;
        float4 h0 = hp4[lane];
        float4 h1 = hp4[lane + 32];
        m0 += h0.x * ax + h0.y * ay + h0.z * az + h0.w * aw;
        m1 += h1.x * ax + h1.y * ay + h1.z * az + h1.w * aw;
    }
    xr[lane]      = m0;
    xr[lane + 32] = m1;
}

// ---------------- fused semantic attention + classifier + log_softmax ----------------
// warp/node; fusion kept in registers, classifier via shfl-broadcast.
#define FC_SMEM ((8192 + 4096 + 10240 + 64) * 4)
__global__ __launch_bounds__(256) void k_fusecls(const float* __restrict__ h,
                                                 const float* __restrict__ w1,
                                                 const float* __restrict__ w2,
                                                 const float* __restrict__ m,
                                                 const float* __restrict__ fc_w,
                                                 const float* __restrict__ fc_b,
                                                 float* __restrict__ out) {
    extern __shared__ float fsm[];
    float* sw1 = fsm;             // 8192
    float* sw2 = sw1 + 8192;      // 4096
    float* sfc = sw2 + 4096;      // 10240
    float* sb  = sfc + 10240;     // 40
    int tid = threadIdx.x;
    for (int i = tid; i < 8192; i += 256) sw1[i] = w1[i];
    for (int i = tid; i < 4096; i += 256) sw2[i] = w2[i];
    for (int i = tid; i < 10240; i += 256) sfc[i] = fc_w[i];
    if (tid < NC) sb[tid] = fc_b[tid];
    __syncthreads();

    int n    = blockIdx.x * 8 + (tid >> 5);   // 40000 = 5000*8, exact
    int lane = tid & 31;
    const float4* hr = (const float4*)(h + (size_t)n * F_INC);
    float f0 = 0.f, f1 = 0.f;
#pragma unroll 8
    for (int d4 = 0; d4 < 32; d4++) {
        float4 hv = hr[d4];
        int d = d4 * 4;
        f0 += hv.x * sw1[(d + 0) * 64 + lane] + hv.y * sw1[(d + 1) * 64 + lane]
            + hv.z * sw1[(d + 2) * 64 + lane] + hv.w * sw1[(d + 3) * 64 + lane];
        f1 += hv.x * sw1[(d + 0) * 64 + lane + 32] + hv.y * sw1[(d + 1) * 64 + lane + 32]
            + hv.z * sw1[(d + 2) * 64 + lane + 32] + hv.w * sw1[(d + 3) * 64 + lane + 32];
    }
    float ml = m[lane], mh = m[lane + 32];
    float ta0[KK], ta1[KK], sc[KK];
#pragma unroll
    for (int k = 0; k < KK; k++) {
        const float* xr = g_x + ((size_t)k * N_USERC + n) * 64;
        float t0 = xr[lane];
        float t1 = xr[lane + 32];
        ta0[k] = t0; ta1[k] = t1;
        float q0 = f0, q1 = f1;
#pragma unroll 8
        for (int g = 0; g < 32; g++) {
            float tv = __shfl_sync(0xffffffffu, t0, g);
            q0 += tv * sw2[g * 64 + lane];
            q1 += tv * sw2[g * 64 + lane + 32];
        }
#pragma unroll 8
        for (int g = 0; g < 32; g++) {
            float tv = __shfl_sync(0xffffffffu, t1, g);
            q0 += tv * sw2[(g + 32) * 64 + lane];
            q1 += tv * sw2[(g + 32) * 64 + lane + 32];
        }
        q0 = tanhf(q0);
        q1 = tanhf(q1);
        float s = q0 * ml + q1 * mh;
#pragma unroll
        for (int off = 16; off; off >>= 1) s += __shfl_xor_sync(0xffffffffu, s, off);
        sc[k] = s;
    }
    float mx = fmaxf(sc[0], fmaxf(sc[1], sc[2]));
    float e0 = __expf(sc[0] - mx), e1 = __expf(sc[1] - mx), e2 = __expf(sc[2] - mx);
    float inv = 1.f / (e0 + e1 + e2);
    float b0 = e0 * inv, b1 = e1 * inv, b2 = e2 * inv;
    float fus0 = b0 * ta0[0] + b1 * ta0[1] + b2 * ta0[2];
    float fus1 = b0 * ta1[0] + b1 * ta1[1] + b2 * ta1[2];

    // ---- classifier: logits[c] = sum_j ret[j] * fc[j][c], ret in registers ----
    float a0 = sb[lane];
    float a1 = (lane < 8) ? sb[lane + 32] : 0.f;
#pragma unroll
    for (int k = 0; k < KK; k++) {
#pragma unroll 8
        for (int f = 0; f < 32; f++) {
            float v = __shfl_sync(0xffffffffu, ta0[k], f);
            const float* row = sfc + (k * 64 + f) * NC;
            a0 += v * row[lane];
            if (lane < 8) a1 += v * row[lane + 32];
        }
#pragma unroll 8
        for (int f = 0; f < 32; f++) {
            float v = __shfl_sync(0xffffffffu, ta1[k], f);
            const float* row = sfc + (k * 64 + 32 + f) * NC;
            a0 += v * row[lane];
            if (lane < 8) a1 += v * row[lane + 32];
        }
    }
#pragma unroll 8
    for (int f = 0; f < 32; f++) {
        float v = __shfl_sync(0xffffffffu, fus0, f);
        const float* row = sfc + (192 + f) * NC;
        a0 += v * row[lane];
        if (lane < 8) a1 += v * row[lane + 32];
    }
#pragma unroll 8
    for (int f = 0; f < 32; f++) {
        float v = __shfl_sync(0xffffffffu, fus1, f);
        const float* row = sfc + (224 + f) * NC;
        a0 += v * row[lane];
        if (lane < 8) a1 += v * row[lane + 32];
    }

    // log_softmax over 40 logits (a0: c=lane; a1: c=lane+32, lane<8)
    float vm = a0;
    if (lane < 8) vm = fmaxf(vm, a1);
#pragma unroll
    for (int off = 16; off; off >>= 1) vm = fmaxf(vm, __shfl_xor_sync(0xffffffffu, vm, off));
    float se = expf(a0 - vm) + ((lane < 8) ? expf(a1 - vm) : 0.f);
#pragma unroll
    for (int off = 16; off; off >>= 1) se += __shfl_xor_sync(0xffffffffu, se, off);
    float ls = vm + logf(se);
    out[(size_t)n * NC + lane] = a0 - ls;
    if (lane < 8) out[(size_t)n * NC + lane + 32] = a1 - ls;
}

// ---------------- launch ----------------
extern "C" void kernel_launch(void* const* d_in, const int* in_sizes, int n_in,
                              void* d_out, int out_size) {
    (void)in_sizes; (void)n_in; (void)out_size;
    const float* h   = (const float*)d_in[0];
    const int*   ei  = (const int*)d_in[1];
    const float* w   = (const float*)d_in[2];
    const float* a_s = (const float*)d_in[3];
    const float* a_t = (const float*)d_in[4];
    const float* w1  = (const float*)d_in[5];
    const float* w2  = (const float*)d_in[6];
    const float* m   = (const float*)d_in[7];
    const float* fcw = (const float*)d_in[8];
    const float* fcb = (const float*)d_in[9];
    float* out = (float*)d_out;

    cudaFuncSetAttribute(k_gemm, cudaFuncAttributeMaxDynamicSharedMemorySize, SMEM_DYN);
    cudaFuncSetAttribute(k_fusecls, cudaFuncAttributeMaxDynamicSharedMemorySize, FC_SMEM);

    // order chosen so the 4th launch (ncu capture slot) is k_gemm
    k_zero   <<<(KK * N_USERC + 255) / 256, 256>>>();
    k_fill   <<<(KK * NE + 255) / 256, 256>>>(ei);
    k_prepB  <<<(KK * 16384 + 255) / 256, 256>>>(w);
    k_gemm   <<<dim3((N_NODES + 63) / 64, KK), 256, SMEM_DYN>>>(h, a_s, a_t);
    k_agg    <<<(KK * N_USERC * 32) / 256, 256>>>();
    k_fusecls<<<N_USERC / 8, 256, FC_SMEM>>>(h, w1, w2, m, fcw, fcb, out);
}

// round 15
// speedup vs baseline: 1.7560x; 1.7560x over previous
#include <cuda_runtime.h>
#include <cstdint>

#define N_NODES 50000
#define N_USERC 40000
#define NE      400000
#define KK      3
#define NH      4
#define F_INC   128
#define F_OUTC  64
#define NC      40
#define SLOPE   0.2f
#define CAP     64

// ---------------- scratch (device globals; no allocations) ----------------
// hp layout: [k][n][f][h]  (head-minor so 4 heads load as one float4)
__device__ float g_hp [(size_t)KK * N_NODES * 256];   // 153.6 MB
__device__ float g_s  [KK * N_NODES * 4];
__device__ float g_t  [KK * N_NODES * 4];
__device__ float g_x  [KK * N_USERC * 64];
__device__ float g_fus[N_USERC * 64];
__device__ int   g_cnt[KK * N_USERC];
__device__ int   g_adj[(size_t)KK * N_USERC * CAP];
// B weights pre-arranged in m16n8k8 tf32 fragment order:
// g_bfrag[k][ ((ch*16+ks)*16+nt)*32 + lane ] = { B[ks*8+lane%4][c], B[ks*8+lane%4+4][c] }
// where c = ch*128 + nt*8 + lane/4 and B[d][c] = w[k][c&3][d][c>>2]   (tf32 bits)
__device__ uint2 g_bfrag[KK * 16384];                 // 384 KB (L2-resident, broadcast)

__device__ __forceinline__ uint32_t f2tf32(float f) {
    uint32_t r;
    asm("cvt.rna.tf32.f32 %0, %1;" : "=r"(r) : "f"(f));
    return r;
}

__device__ __forceinline__ void mma_tf32(float* d, const uint32_t* a, uint2 b) {
    asm volatile(
        "mma.sync.aligned.m16n8k8.row.col.f32.tf32.tf32.f32 "
        "{%0,%1,%2,%3}, {%4,%5,%6,%7}, {%8,%9}, {%0,%1,%2,%3};\n"
        : "+f"(d[0]), "+f"(d[1]), "+f"(d[2]), "+f"(d[3])
        : "r"(a[0]), "r"(a[1]), "r"(a[2]), "r"(a[3]), "r"(b.x), "r"(b.y));
}

// ---------------- zero degree counters ----------------
__global__ void k_zero() {
    int i = blockIdx.x * blockDim.x + threadIdx.x;
    if (i < KK * N_USERC) g_cnt[i] = 0;
}

// ---------------- build per-target adjacency buckets ----------------
__global__ void k_fill(const int* __restrict__ ei) {
    int idx = blockIdx.x * blockDim.x + threadIdx.x;
    if (idx >= KK * NE) return;
    int k = idx / NE;
    int e = idx - k * NE;
    int trg = ei[(k * 2 + 1) * NE + e];
    if (trg >= N_USERC) return;
    int src = ei[(k * 2) * NE + e];
    int slot = k * N_USERC + trg;
    int pos = atomicAdd(&g_cnt[slot], 1);
    if (pos < CAP) g_adj[(size_t)slot * CAP + pos] = src;
}

// ---------------- pre-arrange B into fragment order (runs once, tiny) ----------------
__global__ void k_prepB(const float* __restrict__ w) {
    int id = blockIdx.x * blockDim.x + threadIdx.x;
    if (id >= KK * 16384) return;
    int kk   = id / 16384;
    int r    = id - kk * 16384;
    int lane = r & 31;
    int nt   = (r >> 5) & 15;
    int ks   = (r >> 9) & 15;
    int ch   = r >> 13;
    int d0   = ks * 8 + (lane & 3);
    int c    = ch * 128 + nt * 8 + (lane >> 2);
    int f    = c >> 2, hh = c & 3;
    const float* wk = w + (size_t)kk * NH * F_INC * F_OUTC;
    uint2 b;
    b.x = f2tf32(wk[((size_t)hh * F_INC + d0) * F_OUTC + f]);
    b.y = f2tf32(wk[((size_t)hh * F_INC + d0 + 4) * F_OUTC + f]);
    g_bfrag[id] = b;
}

// ================= tensor-core tf32 GEMM: hp = h @ w[k] + fused s,t =================
// CTA: 64 rows x 256 cols x K=128. 8 warps = 4 row-tiles x 2 col-halves.
// B fragments loaded directly from L2-resident g_bfrag (no SMEM stage) ->
// SMEM drops to ~40KB, __launch_bounds__(256,2) -> 2 CTAs/SM, 16 warps.
#define A_PAD   132                      // 128 + 4 floats, bank-conflict-free frags
#define A_BYTES (64 * A_PAD * 4)         // 33792
#define SMEM_DYN (A_BYTES + 6144)

__global__ __launch_bounds__(256, 2)
void k_gemm(const float* __restrict__ h, const float* __restrict__ a_src,
            const float* __restrict__ a_trg) {
    extern __shared__ __align__(16) char base[];
    float* Asm    = (float*)base;
    float* s_asr  = (float*)(base + A_BYTES);                    // 256
    float* s_atr  = s_asr + 256;                                 // 256
    float* sred_s = s_atr + 256;                                 // 512
    float* sred_t = sred_s + 512;                                // 512

    const int k    = blockIdx.y;
    const int n0   = blockIdx.x * 64;
    const int tid  = threadIdx.x;
    const int wid  = tid >> 5;
    const int lane = tid & 31;
    const int rt   = wid & 3;       // row tile
    const int ch   = wid >> 2;      // col half
    const int g    = lane >> 2;     // group (row within tile)
    const int c    = lane & 3;      // thread-in-group

    // reordered attention coefficient tables: [c] = a[k][c&3][c>>2]
    if (tid < 256) {
        s_asr[tid] = a_src[k * 256 + (tid & 3) * 64 + (tid >> 2)];
        s_atr[tid] = a_trg[k * 256 + (tid & 3) * 64 + (tid >> 2)];
    }

    // stage A (64x128 fp32 -> tf32, padded rows)
    for (int idx = tid; idx < 64 * 32; idx += 256) {
        int row = idx >> 5;
        int c4  = idx & 31;
        int n   = n0 + row;
        float4 av = make_float4(0.f, 0.f, 0.f, 0.f);
        if (n < N_NODES) av = *(const float4*)(h + (size_t)n * F_INC + c4 * 4);
        uint4 tv;
        tv.x = f2tf32(av.x); tv.y = f2tf32(av.y); tv.z = f2tf32(av.z); tv.w = f2tf32(av.w);
        *(uint4*)(Asm + row * A_PAD + c4 * 4) = tv;
    }
    __syncthreads();

    float acc[16][4];
#pragma unroll
    for (int nt = 0; nt < 16; nt++)
#pragma unroll
        for (int j = 0; j < 4; j++) acc[nt][j] = 0.f;

    const float* arow = Asm + (rt * 16 + g) * A_PAD;
    const uint2* bwarp = g_bfrag + (size_t)k * 16384 + (ch * 16) * 16 * 32 + lane;
#pragma unroll 2
    for (int ks = 0; ks < 16; ks++) {
        int col = ks * 8 + c;
        uint32_t a[4];
        a[0] = __float_as_uint(arow[col]);
        a[1] = __float_as_uint(arow[8 * A_PAD + col]);
        a[2] = __float_as_uint(arow[col + 4]);
        a[3] = __float_as_uint(arow[8 * A_PAD + col + 4]);
        const uint2* bk = bwarp + (size_t)ks * 16 * 32;
        uint2 b[16];
#pragma unroll
        for (int nt = 0; nt < 16; nt++) b[nt] = bk[nt * 32];   // LDG.64 from L2 (broadcast)
#pragma unroll
        for (int nt = 0; nt < 16; nt++)
            mma_tf32(acc[nt], a, b[nt]);
    }

    // epilogue: hp stores + per-thread s/t partials
    int nrow0 = n0 + rt * 16 + g;
    int nrow1 = nrow0 + 8;
    float sp00 = 0.f, sp01 = 0.f, sp10 = 0.f, sp11 = 0.f;
    float tp00 = 0.f, tp01 = 0.f, tp10 = 0.f, tp11 = 0.f;
    float* hp0 = g_hp + ((size_t)k * N_NODES + nrow0) * 256;
    float* hp1 = g_hp + ((size_t)k * N_NODES + nrow1) * 256;
    bool ok0 = (nrow0 < N_NODES), ok1 = (nrow1 < N_NODES);
#pragma unroll
    for (int nt = 0; nt < 16; nt++) {
        int cb = ch * 128 + nt * 8 + 2 * c;
        float w0 = s_asr[cb], w1 = s_asr[cb + 1];
        float v0 = s_atr[cb], v1 = s_atr[cb + 1];
        sp00 += acc[nt][0] * w0; sp01 += acc[nt][1] * w1;
        sp10 += acc[nt][2] * w0; sp11 += acc[nt][3] * w1;
        tp00 += acc[nt][0] * v0; tp01 += acc[nt][1] * v1;
        tp10 += acc[nt][2] * v0; tp11 += acc[nt][3] * v1;
        if (ok0) *(float2*)(hp0 + cb) = make_float2(acc[nt][0], acc[nt][1]);
        if (ok1) *(float2*)(hp1 + cb) = make_float2(acc[nt][2], acc[nt][3]);
    }
    // quad-reduce: lane c combines with c^2 (same head pair)
    sp00 += __shfl_xor_sync(0xffffffffu, sp00, 2);
    sp01 += __shfl_xor_sync(0xffffffffu, sp01, 2);
    sp10 += __shfl_xor_sync(0xffffffffu, sp10, 2);
    sp11 += __shfl_xor_sync(0xffffffffu, sp11, 2);
    tp00 += __shfl_xor_sync(0xffffffffu, tp00, 2);
    tp01 += __shfl_xor_sync(0xffffffffu, tp01, 2);
    tp10 += __shfl_xor_sync(0xffffffffu, tp10, 2);
    tp11 += __shfl_xor_sync(0xffffffffu, tp11, 2);
    if (c < 2) {
        int b0 = ((wid * 8 + g) * 2 + 0) * 4 + 2 * c;
        int b1 = ((wid * 8 + g) * 2 + 1) * 4 + 2 * c;
        sred_s[b0] = sp00; sred_s[b0 + 1] = sp01;
        sred_s[b1] = sp10; sred_s[b1 + 1] = sp11;
        sred_t[b0] = tp00; sred_t[b0 + 1] = tp01;
        sred_t[b1] = tp10; sred_t[b1 + 1] = tp11;
    }
    __syncthreads();
    // final cross-colhalf combine: tid -> (row, head)
    {
        int row = tid >> 2, hh = tid & 3;
        int n = n0 + row;
        if (n < N_NODES) {
            int rtf = row >> 4, rr = row & 15, gg = rr & 7, r = rr >> 3;
            int i0 = ((rtf * 8 + gg) * 2 + r) * 4 + hh;
            int i1 = (((rtf + 4) * 8 + gg) * 2 + r) * 4 + hh;
            size_t o = ((size_t)k * N_NODES + n) * 4 + hh;
            g_s[o] = sred_s[i0] + sred_s[i1];
            g_t[o] = sred_t[i0] + sred_t[i1];
        }
    }
}

__device__ __forceinline__ float lrelu_exp(float v) {
    v = (v >= 0.f) ? v : SLOPE * v;
    return __expf(v);
}

// ---------------- fused softmax + aggregation (warp per (k,trg)) — R13 form ----------------
__global__ __launch_bounds__(256) void k_agg() {
    int gw   = (blockIdx.x * blockDim.x + threadIdx.x) >> 5;
    int lane = threadIdx.x & 31;
    if (gw >= KK * N_USERC) return;
    int k = gw / N_USERC;
    int n = gw - k * N_USERC;
    float* xr = g_x + (size_t)gw * 64;

    int deg = g_cnt[gw];
    deg = (deg > CAP) ? CAP : deg;
    if (deg == 0) {
        xr[lane] = 0.f;
        xr[lane + 32] = 0.f;
        return;
    }
    float4 tv = *(const float4*)(g_t + ((size_t)k * N_NODES + n) * 4);
    const int* adj = g_adj + (size_t)gw * CAP;

    int src0 = (lane < deg)      ? adj[lane]      : 0;
    int src1 = (lane + 32 < deg) ? adj[lane + 32] : 0;
    float4 ex0 = make_float4(0.f, 0.f, 0.f, 0.f);
    float4 ex1 = make_float4(0.f, 0.f, 0.f, 0.f);
    if (lane < deg) {
        float4 sv = *(const float4*)(g_s + ((size_t)k * N_NODES + src0) * 4);
        ex0.x = lrelu_exp(sv.x + tv.x); ex0.y = lrelu_exp(sv.y + tv.y);
        ex0.z = lrelu_exp(sv.z + tv.z); ex0.w = lrelu_exp(sv.w + tv.w);
    }
    if (lane + 32 < deg) {
        float4 sv = *(const float4*)(g_s + ((size_t)k * N_NODES + src1) * 4);
        ex1.x = lrelu_exp(sv.x + tv.x); ex1.y = lrelu_exp(sv.y + tv.y);
        ex1.z = lrelu_exp(sv.z + tv.z); ex1.w = lrelu_exp(sv.w + tv.w);
    }
    float dx = ex0.x + ex1.x, dy = ex0.y + ex1.y, dz = ex0.z + ex1.z, dw = ex0.w + ex1.w;
#pragma unroll
    for (int off = 16; off; off >>= 1) {
        dx += __shfl_xor_sync(0xffffffffu, dx, off);
        dy += __shfl_xor_sync(0xffffffffu, dy, off);
        dz += __shfl_xor_sync(0xffffffffu, dz, off);
        dw += __shfl_xor_sync(0xffffffffu, dw, off);
    }
    float ix = 0.25f / (dx + 1e-16f);
    float iy = 0.25f / (dy + 1e-16f);
    float iz = 0.25f / (dz + 1e-16f);
    float iw = 0.25f / (dw + 1e-16f);

    const float4* hpb = ((const float4*)g_hp) + (size_t)k * N_NODES * 64;
    float m0 = 0.f, m1 = 0.f;
    int d0 = (deg < 32) ? deg : 32;
    for (int j = 0; j < d0; j++) {
        int   s  = __shfl_sync(0xffffffffu, src0, j);
        float ax = __shfl_sync(0xffffffffu, ex0.x, j) * ix;
        float ay = __shfl_sync(0xffffffffu, ex0.y, j) * iy;
        float az = __shfl_sync(0xffffffffu, ex0.z, j) * iz;
        float aw = __shfl_sync(0xffffffffu, ex0.w, j) * iw;
        const float4* hp4 = hpb + (size_t)s * 64;
        float4 h0 = hp4[lane];
        float4 h1 = hp4[lane + 32];
        m0 += h0.x * ax + h0.y * ay + h0.z * az + h0.w * aw;
        m1 += h1.x * ax + h1.y * ay + h1.z * az + h1.w * aw;
    }
    for (int j = 32; j < deg; j++) {
        int   s  = __shfl_sync(0xffffffffu, src1, j - 32);
        float ax = __shfl_sync(0xffffffffu, ex1.x, j - 32) * ix;
        float ay = __shfl_sync(0xffffffffu, ex1.y, j - 32) * iy;
        float az = __shfl_sync(0xffffffffu, ex1.z, j - 32) * iz;
        float aw = __shfl_sync(0xffffffffu, ex1.w, j - 32) * iw;
        const float4* hp4 = hpb + (size_t)s * 64;
        float4 h0 = hp4[lane];
        float4 h1 = hp4[lane + 32];
        m0 += h0.x * ax + h0.y * ay + h0.z * az + h0.w * aw;
        m1 += h1.x * ax + h1.y * ay + h1.z * az + h1.w * aw;
    }
    xr[lane]      = m0;
    xr[lane + 32] = m1;
}

// ---------------- semantic attention fusion (warp/node) — R13 form ----------------
__global__ __launch_bounds__(256) void k_fuse(const float* __restrict__ h,
                                              const float* __restrict__ w1,
                                              const float* __restrict__ w2,
                                              const float* __restrict__ m) {
    __shared__ float sw1[F_INC * F_OUTC];
    __shared__ float sw2[F_OUTC * F_OUTC];
    int tid = threadIdx.x;
    for (int i = tid; i < F_INC * F_OUTC; i += 256) sw1[i] = w1[i];
    for (int i = tid; i < F_OUTC * F_OUTC; i += 256) sw2[i] = w2[i];
    __syncthreads();

    int n    = blockIdx.x * 8 + (tid >> 5);
    int lane = tid & 31;
    const float4* hr = (const float4*)(h + (size_t)n * F_INC);
    float f0 = 0.f, f1 = 0.f;
#pragma unroll 8
    for (int d4 = 0; d4 < 32; d4++) {
        float4 hv = hr[d4];
        int d = d4 * 4;
        f0 += hv.x * sw1[(d + 0) * 64 + lane] + hv.y * sw1[(d + 1) * 64 + lane]
            + hv.z * sw1[(d + 2) * 64 + lane] + hv.w * sw1[(d + 3) * 64 + lane];
        f1 += hv.x * sw1[(d + 0) * 64 + lane + 32] + hv.y * sw1[(d + 1) * 64 + lane + 32]
            + hv.z * sw1[(d + 2) * 64 + lane + 32] + hv.w * sw1[(d + 3) * 64 + lane + 32];
    }
    float ml = m[lane], mh = m[lane + 32];
    float ta0[KK], ta1[KK], sc[KK];
#pragma unroll
    for (int k = 0; k < KK; k++) {
        const float* xr = g_x + ((size_t)k * N_USERC + n) * 64;
        float t0 = xr[lane];
        float t1 = xr[lane + 32];
        ta0[k] = t0; ta1[k] = t1;
        float q0 = f0, q1 = f1;
#pragma unroll 8
        for (int g = 0; g < 32; g++) {
            float tv = __shfl_sync(0xffffffffu, t0, g);
            q0 += tv * sw2[g * 64 + lane];
            q1 += tv * sw2[g * 64 + lane + 32];
        }
#pragma unroll 8
        for (int g = 0; g < 32; g++) {
            float tv = __shfl_sync(0xffffffffu, t1, g);
            q0 += tv * sw2[(g + 32) * 64 + lane];
            q1 += tv * sw2[(g + 32) * 64 + lane + 32];
        }
        q0 = tanhf(q0);
        q1 = tanhf(q1);
        float s = q0 * ml + q1 * mh;
#pragma unroll
        for (int off = 16; off; off >>= 1) s += __shfl_xor_sync(0xffffffffu, s, off);
        sc[k] = s;
    }
    float mx = fmaxf(sc[0], fmaxf(sc[1], sc[2]));
    float e0 = __expf(sc[0] - mx), e1 = __expf(sc[1] - mx), e2 = __expf(sc[2] - mx);
    float inv = 1.f / (e0 + e1 + e2);
    float b0 = e0 * inv, b1 = e1 * inv, b2 = e2 * inv;
    g_fus[(size_t)n * 64 + lane]      = b0 * ta0[0] + b1 * ta0[1] + b2 * ta0[2];
    g_fus[(size_t)n * 64 + lane + 32] = b0 * ta1[0] + b1 * ta1[1] + b2 * ta1[2];
}

// ---------------- classifier + log_softmax (warp/node) — R13 form ----------------
__global__ __launch_bounds__(256) void k_cls(const float* __restrict__ fc_w,
                                             const float* __restrict__ fc_b,
                                             float* __restrict__ out) {
    __shared__ float sfc[256 * NC];
    __shared__ float sb[NC];
    int tid = threadIdx.x;
    for (int i = tid; i < 256 * NC; i += 256) sfc[i] = fc_w[i];
    if (tid < NC) sb[tid] = fc_b[tid];
    __syncthreads();

    int n    = blockIdx.x * 8 + (tid >> 5);
    int lane = tid & 31;
    float a0 = sb[lane];
    float a1 = (lane < 8) ? sb[lane + 32] : 0.f;

    const float4* x4   = (const float4*)g_x;
    const float4* fus4 = (const float4*)g_fus;
#pragma unroll 4
    for (int j4 = 0; j4 < 64; j4++) {
        float4 rv;
        if (j4 < 48) {
            int k  = j4 >> 4;
            int f4 = j4 & 15;
            rv = x4[((size_t)k * N_USERC + n) * 16 + f4];
        } else {
            rv = fus4[(size_t)n * 16 + (j4 - 48)];
        }
        int j = j4 * 4;
        a0 += rv.x * sfc[(j + 0) * NC + lane];
        a0 += rv.y * sfc[(j + 1) * NC + lane];
        a0 += rv.z * sfc[(j + 2) * NC + lane];
        a0 += rv.w * sfc[(j + 3) * NC + lane];
        if (lane < 8) {
            a1 += rv.x * sfc[(j + 0) * NC + lane + 32];
            a1 += rv.y * sfc[(j + 1) * NC + lane + 32];
            a1 += rv.z * sfc[(j + 2) * NC + lane + 32];
            a1 += rv.w * sfc[(j + 3) * NC + lane + 32];
        }
    }
    float vm = a0;
    if (lane < 8) vm = fmaxf(vm, a1);
#pragma unroll
    for (int off = 16; off; off >>= 1) vm = fmaxf(vm, __shfl_xor_sync(0xffffffffu, vm, off));
    float se = expf(a0 - vm) + ((lane < 8) ? expf(a1 - vm) : 0.f);
#pragma unroll
    for (int off = 16; off; off >>= 1) se += __shfl_xor_sync(0xffffffffu, se, off);
    float ls = vm + logf(se);
    out[(size_t)n * NC + lane] = a0 - ls;
    if (lane < 8) out[(size_t)n * NC + lane + 32] = a1 - ls;
}

// ---------------- launch ----------------
extern "C" void kernel_launch(void* const* d_in, const int* in_sizes, int n_in,
                              void* d_out, int out_size) {
    (void)in_sizes; (void)n_in; (void)out_size;
    const float* h   = (const float*)d_in[0];
    const int*   ei  = (const int*)d_in[1];
    const float* w   = (const float*)d_in[2];
    const float* a_s = (const float*)d_in[3];
    const float* a_t = (const float*)d_in[4];
    const float* w1  = (const float*)d_in[5];
    const float* w2  = (const float*)d_in[6];
    const float* m   = (const float*)d_in[7];
    const float* fcw = (const float*)d_in[8];
    const float* fcb = (const float*)d_in[9];
    float* out = (float*)d_out;

    cudaFuncSetAttribute(k_gemm, cudaFuncAttributeMaxDynamicSharedMemorySize, SMEM_DYN);

    // order keeps k_gemm in the 4th (ncu-captured) slot
    k_zero <<<(KK * N_USERC + 255) / 256, 256>>>();
    k_fill <<<(KK * NE + 255) / 256, 256>>>(ei);
    k_prepB<<<(KK * 16384 + 255) / 256, 256>>>(w);
    k_gemm <<<dim3((N_NODES + 63) / 64, KK), 256, SMEM_DYN>>>(h, a_s, a_t);
    k_agg  <<<(KK * N_USERC * 32) / 256, 256>>>();
    k_fuse <<<N_USERC / 8, 256>>>(h, w1, w2, m);
    k_cls  <<<N_USERC / 8, 256>>>(fcw, fcb, out);
}

// round 16
// speedup vs baseline: 1.7760x; 1.0114x over previous
#include <cuda_runtime.h>
#include <cstdint>

#define N_NODES 50000
#define N_USERC 40000
#define NE      400000
#define KK      3
#define NH      4
#define F_INC   128
#define F_OUTC  64
#define NC      40
#define SLOPE   0.2f
#define CAP     64

// ---------------- scratch (device globals; no allocations) ----------------
// hp layout: [k][n][f][h]  (head-minor so 4 heads load as one float4)
__device__ float g_hp [(size_t)KK * N_NODES * 256];   // 153.6 MB
__device__ float g_s  [KK * N_NODES * 4];
__device__ float g_t  [KK * N_NODES * 4];
__device__ float g_x  [KK * N_USERC * 64];
__device__ int   g_cnt[KK * N_USERC];                 // zero at rest: agg re-zeroes after read
__device__ int   g_adj[(size_t)KK * N_USERC * CAP];
// B weights pre-arranged in m16n8k8 tf32 fragment order (L2-resident, broadcast)
__device__ uint2 g_bfrag[KK * 16384];                 // 384 KB

__device__ __forceinline__ uint32_t f2tf32(float f) {
    uint32_t r;
    asm("cvt.rna.tf32.f32 %0, %1;" : "=r"(r) : "f"(f));
    return r;
}

__device__ __forceinline__ void mma_tf32(float* d, const uint32_t* a, uint2 b) {
    asm volatile(
        "mma.sync.aligned.m16n8k8.row.col.f32.tf32.tf32.f32 "
        "{%0,%1,%2,%3}, {%4,%5,%6,%7}, {%8,%9}, {%0,%1,%2,%3};\n"
        : "+f"(d[0]), "+f"(d[1]), "+f"(d[2]), "+f"(d[3])
        : "r"(a[0]), "r"(a[1]), "r"(a[2]), "r"(a[3]), "r"(b.x), "r"(b.y));
}

// ---------------- merged: adjacency fill + B fragment prep ----------------
// blocks [0, PREP_BLOCKS): prepB ; blocks [PREP_BLOCKS, ...): edge fill
#define PREP_BLOCKS ((KK * 16384 + 255) / 256)
#define FILL_BLOCKS ((KK * NE + 255) / 256)
__global__ void k_fillprep(const int* __restrict__ ei, const float* __restrict__ w) {
    int b = blockIdx.x;
    if (b < PREP_BLOCKS) {
        int id = b * 256 + threadIdx.x;
        if (id >= KK * 16384) return;
        int kk   = id / 16384;
        int r    = id - kk * 16384;
        int lane = r & 31;
        int nt   = (r >> 5) & 15;
        int ks   = (r >> 9) & 15;
        int ch   = r >> 13;
        int d0   = ks * 8 + (lane & 3);
        int c    = ch * 128 + nt * 8 + (lane >> 2);
        int f    = c >> 2, hh = c & 3;
        const float* wk = w + (size_t)kk * NH * F_INC * F_OUTC;
        uint2 bb;
        bb.x = f2tf32(wk[((size_t)hh * F_INC + d0) * F_OUTC + f]);
        bb.y = f2tf32(wk[((size_t)hh * F_INC + d0 + 4) * F_OUTC + f]);
        g_bfrag[id] = bb;
    } else {
        int idx = (b - PREP_BLOCKS) * 256 + threadIdx.x;
        if (idx >= KK * NE) return;
        int k = idx / NE;
        int e = idx - k * NE;
        int trg = ei[(k * 2 + 1) * NE + e];
        if (trg >= N_USERC) return;
        int src = ei[(k * 2) * NE + e];
        int slot = k * N_USERC + trg;
        int pos = atomicAdd(&g_cnt[slot], 1);
        if (pos < CAP) g_adj[(size_t)slot * CAP + pos] = src;
    }
}

// ================= tensor-core tf32 GEMM: hp = h @ w[k] + fused s,t (R15 form) ============
#define A_PAD   132
#define A_BYTES (64 * A_PAD * 4)         // 33792
#define SMEM_DYN (A_BYTES + 6144)

__global__ __launch_bounds__(256, 2)
void k_gemm(const float* __restrict__ h, const float* __restrict__ a_src,
            const float* __restrict__ a_trg) {
    extern __shared__ __align__(16) char base[];
    float* Asm    = (float*)base;
    float* s_asr  = (float*)(base + A_BYTES);                    // 256
    float* s_atr  = s_asr + 256;                                 // 256
    float* sred_s = s_atr + 256;                                 // 512
    float* sred_t = sred_s + 512;                                // 512

    const int k    = blockIdx.y;
    const int n0   = blockIdx.x * 64;
    const int tid  = threadIdx.x;
    const int wid  = tid >> 5;
    const int lane = tid & 31;
    const int rt   = wid & 3;
    const int ch   = wid >> 2;
    const int g    = lane >> 2;
    const int c    = lane & 3;

    if (tid < 256) {
        s_asr[tid] = a_src[k * 256 + (tid & 3) * 64 + (tid >> 2)];
        s_atr[tid] = a_trg[k * 256 + (tid & 3) * 64 + (tid >> 2)];
    }

    for (int idx = tid; idx < 64 * 32; idx += 256) {
        int row = idx >> 5;
        int c4  = idx & 31;
        int n   = n0 + row;
        float4 av = make_float4(0.f, 0.f, 0.f, 0.f);
        if (n < N_NODES) av = *(const float4*)(h + (size_t)n * F_INC + c4 * 4);
        uint4 tv;
        tv.x = f2tf32(av.x); tv.y = f2tf32(av.y); tv.z = f2tf32(av.z); tv.w = f2tf32(av.w);
        *(uint4*)(Asm + row * A_PAD + c4 * 4) = tv;
    }
    __syncthreads();

    float acc[16][4];
#pragma unroll
    for (int nt = 0; nt < 16; nt++)
#pragma unroll
        for (int j = 0; j < 4; j++) acc[nt][j] = 0.f;

    const float* arow = Asm + (rt * 16 + g) * A_PAD;
    const uint2* bwarp = g_bfrag + (size_t)k * 16384 + (ch * 16) * 16 * 32 + lane;
#pragma unroll 2
    for (int ks = 0; ks < 16; ks++) {
        int col = ks * 8 + c;
        uint32_t a[4];
        a[0] = __float_as_uint(arow[col]);
        a[1] = __float_as_uint(arow[8 * A_PAD + col]);
        a[2] = __float_as_uint(arow[col + 4]);
        a[3] = __float_as_uint(arow[8 * A_PAD + col + 4]);
        const uint2* bk = bwarp + (size_t)ks * 16 * 32;
        uint2 b[16];
#pragma unroll
        for (int nt = 0; nt < 16; nt++) b[nt] = bk[nt * 32];
#pragma unroll
        for (int nt = 0; nt < 16; nt++)
            mma_tf32(acc[nt], a, b[nt]);
    }

    int nrow0 = n0 + rt * 16 + g;
    int nrow1 = nrow0 + 8;
    float sp00 = 0.f, sp01 = 0.f, sp10 = 0.f, sp11 = 0.f;
    float tp00 = 0.f, tp01 = 0.f, tp10 = 0.f, tp11 = 0.f;
    float* hp0 = g_hp + ((size_t)k * N_NODES + nrow0) * 256;
    float* hp1 = g_hp + ((size_t)k * N_NODES + nrow1) * 256;
    bool ok0 = (nrow0 < N_NODES), ok1 = (nrow1 < N_NODES);
#pragma unroll
    for (int nt = 0; nt < 16; nt++) {
        int cb = ch * 128 + nt * 8 + 2 * c;
        float w0 = s_asr[cb], w1 = s_asr[cb + 1];
        float v0 = s_atr[cb], v1 = s_atr[cb + 1];
        sp00 += acc[nt][0] * w0; sp01 += acc[nt][1] * w1;
        sp10 += acc[nt][2] * w0; sp11 += acc[nt][3] * w1;
        tp00 += acc[nt][0] * v0; tp01 += acc[nt][1] * v1;
        tp10 += acc[nt][2] * v0; tp11 += acc[nt][3] * v1;
        if (ok0) *(float2*)(hp0 + cb) = make_float2(acc[nt][0], acc[nt][1]);
        if (ok1) *(float2*)(hp1 + cb) = make_float2(acc[nt][2], acc[nt][3]);
    }
    sp00 += __shfl_xor_sync(0xffffffffu, sp00, 2);
    sp01 += __shfl_xor_sync(0xffffffffu, sp01, 2);
    sp10 += __shfl_xor_sync(0xffffffffu, sp10, 2);
    sp11 += __shfl_xor_sync(0xffffffffu, sp11, 2);
    tp00 += __shfl_xor_sync(0xffffffffu, tp00, 2);
    tp01 += __shfl_xor_sync(0xffffffffu, tp01, 2);
    tp10 += __shfl_xor_sync(0xffffffffu, tp10, 2);
    tp11 += __shfl_xor_sync(0xffffffffu, tp11, 2);
    if (c < 2) {
        int b0 = ((wid * 8 + g) * 2 + 0) * 4 + 2 * c;
        int b1 = ((wid * 8 + g) * 2 + 1) * 4 + 2 * c;
        sred_s[b0] = sp00; sred_s[b0 + 1] = sp01;
        sred_s[b1] = sp10; sred_s[b1 + 1] = sp11;
        sred_t[b0] = tp00; sred_t[b0 + 1] = tp01;
        sred_t[b1] = tp10; sred_t[b1 + 1] = tp11;
    }
    __syncthreads();
    {
        int row = tid >> 2, hh = tid & 3;
        int n = n0 + row;
        if (n < N_NODES) {
            int rtf = row >> 4, rr = row & 15, gg = rr & 7, r = rr >> 3;
            int i0 = ((rtf * 8 + gg) * 2 + r) * 4 + hh;
            int i1 = (((rtf + 4) * 8 + gg) * 2 + r) * 4 + hh;
            size_t o = ((size_t)k * N_NODES + n) * 4 + hh;
            g_s[o] = sred_s[i0] + sred_s[i1];
            g_t[o] = sred_t[i0] + sred_t[i1];
        }
    }
}

__device__ __forceinline__ float lrelu_exp(float v) {
    v = (v >= 0.f) ? v : SLOPE * v;
    return __expf(v);
}

// ---------------- fused softmax + aggregation (warp per (k,trg)) ----------------
// NOTE: resets g_cnt[gw] to 0 after reading (replaces k_zero; deterministic per replay).
__global__ __launch_bounds__(256) void k_agg() {
    int gw   = (blockIdx.x * blockDim.x + threadIdx.x) >> 5;
    int lane = threadIdx.x & 31;
    if (gw >= KK * N_USERC) return;
    int k = gw / N_USERC;
    int n = gw - k * N_USERC;
    float* xr = g_x + (size_t)gw * 64;

    int deg = g_cnt[gw];
    if (lane == 0 && deg != 0) g_cnt[gw] = 0;   // reset for next invocation
    deg = (deg > CAP) ? CAP : deg;
    if (deg == 0) {
        xr[lane] = 0.f;
        xr[lane + 32] = 0.f;
        return;
    }
    float4 tv = *(const float4*)(g_t + ((size_t)k * N_NODES + n) * 4);
    const int* adj = g_adj + (size_t)gw * CAP;

    int src0 = (lane < deg)      ? adj[lane]      : 0;
    int src1 = (lane + 32 < deg) ? adj[lane + 32] : 0;
    float4 ex0 = make_float4(0.f, 0.f, 0.f, 0.f);
    float4 ex1 = make_float4(0.f, 0.f, 0.f, 0.f);
    if (lane < deg) {
        float4 sv = *(const float4*)(g_s + ((size_t)k * N_NODES + src0) * 4);
        ex0.x = lrelu_exp(sv.x + tv.x); ex0.y = lrelu_exp(sv.y + tv.y);
        ex0.z = lrelu_exp(sv.z + tv.z); ex0.w = lrelu_exp(sv.w + tv.w);
    }
    if (lane + 32 < deg) {
        float4 sv = *(const float4*)(g_s + ((size_t)k * N_NODES + src1) * 4);
        ex1.x = lrelu_exp(sv.x + tv.x); ex1.y = lrelu_exp(sv.y + tv.y);
        ex1.z = lrelu_exp(sv.z + tv.z); ex1.w = lrelu_exp(sv.w + tv.w);
    }
    float dx = ex0.x + ex1.x, dy = ex0.y + ex1.y, dz = ex0.z + ex1.z, dw = ex0.w + ex1.w;
#pragma unroll
    for (int off = 16; off; off >>= 1) {
        dx += __shfl_xor_sync(0xffffffffu, dx, off);
        dy += __shfl_xor_sync(0xffffffffu, dy, off);
        dz += __shfl_xor_sync(0xffffffffu, dz, off);
        dw += __shfl_xor_sync(0xffffffffu, dw, off);
    }
    float ix = 0.25f / (dx + 1e-16f);
    float iy = 0.25f / (dy + 1e-16f);
    float iz = 0.25f / (dz + 1e-16f);
    float iw = 0.25f / (dw + 1e-16f);

    const float4* hpb = ((const float4*)g_hp) + (size_t)k * N_NODES * 64;
    float m0 = 0.f, m1 = 0.f;
    int d0 = (deg < 32) ? deg : 32;
    for (int j = 0; j < d0; j++) {
        int   s  = __shfl_sync(0xffffffffu, src0, j);
        float ax = __shfl_sync(0xffffffffu, ex0.x, j) * ix;
        float ay = __shfl_sync(0xffffffffu, ex0.y, j) * iy;
        float az = __shfl_sync(0xffffffffu, ex0.z, j) * iz;
        float aw = __shfl_sync(0xffffffffu, ex0.w, j) * iw;
        const float4* hp4 = hpb + (size_t)s * 64;
        float4 h0 = hp4[lane];
        float4 h1 = hp4[lane + 32];
        m0 += h0.x * ax + h0.y * ay + h0.z * az + h0.w * aw;
        m1 += h1.x * ax + h1.y * ay + h1.z * az + h1.w * aw;
    }
    for (int j = 32; j < deg; j++) {
        int   s  = __shfl_sync(0xffffffffu, src1, j - 32);
        float ax = __shfl_sync(0xffffffffu, ex1.x, j - 32) * ix;
        float ay = __shfl_sync(0xffffffffu, ex1.y, j - 32) * iy;
        float az = __shfl_sync(0xffffffffu, ex1.z, j - 32) * iz;
        float aw = __shfl_sync(0xffffffffu, ex1.w, j - 32) * iw;
        const float4* hp4 = hpb + (size_t)s * 64;
        float4 h0 = hp4[lane];
        float4 h1 = hp4[lane + 32];
        m0 += h0.x * ax + h0.y * ay + h0.z * az + h0.w * aw;
        m1 += h1.x * ax + h1.y * ay + h1.z * az + h1.w * aw;
    }
    xr[lane]      = m0;
    xr[lane + 32] = m1;
}

// ---------------- fused semantic attention + classifier + log_softmax ----------------
// warp/node. fusion in registers; fc_w read via __ldg (L1-hot, 40KB), SMEM = 48KB exactly.
__global__ __launch_bounds__(256) void k_fusecls(const float* __restrict__ h,
                                                 const float* __restrict__ w1,
                                                 const float* __restrict__ w2,
                                                 const float* __restrict__ m,
                                                 const float* __restrict__ fc_w,
                                                 const float* __restrict__ fc_b,
                                                 float* __restrict__ out) {
    __shared__ float sw1[F_INC * F_OUTC];   // 32 KB
    __shared__ float sw2[F_OUTC * F_OUTC];  // 16 KB
    int tid = threadIdx.x;
    for (int i = tid; i < F_INC * F_OUTC; i += 256) sw1[i] = w1[i];
    for (int i = tid; i < F_OUTC * F_OUTC; i += 256) sw2[i] = w2[i];
    __syncthreads();

    int n    = blockIdx.x * 8 + (tid >> 5);   // 40000 = 5000*8, exact
    int lane = tid & 31;
    const float4* hr = (const float4*)(h + (size_t)n * F_INC);
    float f0 = 0.f, f1 = 0.f;
#pragma unroll 8
    for (int d4 = 0; d4 < 32; d4++) {
        float4 hv = hr[d4];
        int d = d4 * 4;
        f0 += hv.x * sw1[(d + 0) * 64 + lane] + hv.y * sw1[(d + 1) * 64 + lane]
            + hv.z * sw1[(d + 2) * 64 + lane] + hv.w * sw1[(d + 3) * 64 + lane];
        f1 += hv.x * sw1[(d + 0) * 64 + lane + 32] + hv.y * sw1[(d + 1) * 64 + lane + 32]
            + hv.z * sw1[(d + 2) * 64 + lane + 32] + hv.w * sw1[(d + 3) * 64 + lane + 32];
    }
    float ml = __ldg(m + lane), mh = __ldg(m + lane + 32);
    float ta0[KK], ta1[KK], sc[KK];
#pragma unroll
    for (int k = 0; k < KK; k++) {
        const float* xr = g_x + ((size_t)k * N_USERC + n) * 64;
        float t0 = xr[lane];
        float t1 = xr[lane + 32];
        ta0[k] = t0; ta1[k] = t1;
        float q0 = f0, q1 = f1;
#pragma unroll 8
        for (int g = 0; g < 32; g++) {
            float tv = __shfl_sync(0xffffffffu, t0, g);
            q0 += tv * sw2[g * 64 + lane];
            q1 += tv * sw2[g * 64 + lane + 32];
        }
#pragma unroll 8
        for (int g = 0; g < 32; g++) {
            float tv = __shfl_sync(0xffffffffu, t1, g);
            q0 += tv * sw2[(g + 32) * 64 + lane];
            q1 += tv * sw2[(g + 32) * 64 + lane + 32];
        }
        q0 = tanhf(q0);
        q1 = tanhf(q1);
        float s = q0 * ml + q1 * mh;
#pragma unroll
        for (int off = 16; off; off >>= 1) s += __shfl_xor_sync(0xffffffffu, s, off);
        sc[k] = s;
    }
    float mx = fmaxf(sc[0], fmaxf(sc[1], sc[2]));
    float e0 = __expf(sc[0] - mx), e1 = __expf(sc[1] - mx), e2 = __expf(sc[2] - mx);
    float inv = 1.f / (e0 + e1 + e2);
    float b0 = e0 * inv, b1 = e1 * inv, b2 = e2 * inv;
    float fus0 = b0 * ta0[0] + b1 * ta0[1] + b2 * ta0[2];
    float fus1 = b0 * ta1[0] + b1 * ta1[1] + b2 * ta1[2];

    // ---- classifier: logits[c] = fc_b[c] + sum_j ret[j]*fc_w[j][c]; fc via L1 ----
    float a0 = __ldg(fc_b + lane);                       // classes 0..31
    float a1 = (lane < 8) ? __ldg(fc_b + lane + 32) : 0.f;  // classes 32..39
#pragma unroll
    for (int k = 0; k < KK; k++) {
#pragma unroll 8
        for (int f = 0; f < 32; f++) {
            float v = __shfl_sync(0xffffffffu, ta0[k], f);
            const float* row = fc_w + (k * 64 + f) * NC;
            a0 += v * __ldg(row + lane);
            if (lane < 8) a1 += v * __ldg(row + lane + 32);
        }
#pragma unroll 8
        for (int f = 0; f < 32; f++) {
            float v = __shfl_sync(0xffffffffu, ta1[k], f);
            const float* row = fc_w + (k * 64 + 32 + f) * NC;
            a0 += v * __ldg(row + lane);
            if (lane < 8) a1 += v * __ldg(row + lane + 32);
        }
    }
#pragma unroll 8
    for (int f = 0; f < 32; f++) {
        float v = __shfl_sync(0xffffffffu, fus0, f);
        const float* row = fc_w + (192 + f) * NC;
        a0 += v * __ldg(row + lane);
        if (lane < 8) a1 += v * __ldg(row + lane + 32);
    }
#pragma unroll 8
    for (int f = 0; f < 32; f++) {
        float v = __shfl_sync(0xffffffffu, fus1, f);
        const float* row = fc_w + (224 + f) * NC;
        a0 += v * __ldg(row + lane);
        if (lane < 8) a1 += v * __ldg(row + lane + 32);
    }

    // log_softmax over 40 logits (a0: c=lane; a1: c=lane+32, lane<8)
    float vm = a0;
    if (lane < 8) vm = fmaxf(vm, a1);
#pragma unroll
    for (int off = 16; off; off >>= 1) vm = fmaxf(vm, __shfl_xor_sync(0xffffffffu, vm, off));
    float se = expf(a0 - vm) + ((lane < 8) ? expf(a1 - vm) : 0.f);
#pragma unroll
    for (int off = 16; off; off >>= 1) se += __shfl_xor_sync(0xffffffffu, se, off);
    float ls = vm + logf(se);
    out[(size_t)n * NC + lane] = a0 - ls;
    if (lane < 8) out[(size_t)n * NC + lane + 32] = a1 - ls;
}

// ---------------- launch ----------------
extern "C" void kernel_launch(void* const* d_in, const int* in_sizes, int n_in,
                              void* d_out, int out_size) {
    (void)in_sizes; (void)n_in; (void)out_size;
    const float* h   = (const float*)d_in[0];
    const int*   ei  = (const int*)d_in[1];
    const float* w   = (const float*)d_in[2];
    const float* a_s = (const float*)d_in[3];
    const float* a_t = (const float*)d_in[4];
    const float* w1  = (const float*)d_in[5];
    const float* w2  = (const float*)d_in[6];
    const float* m   = (const float*)d_in[7];
    const float* fcw = (const float*)d_in[8];
    const float* fcb = (const float*)d_in[9];
    float* out = (float*)d_out;

    cudaFuncSetAttribute(k_gemm, cudaFuncAttributeMaxDynamicSharedMemorySize, SMEM_DYN);

    // 4 kernels; ncu capture slot (4th launch) = k_fusecls
    k_fillprep<<<PREP_BLOCKS + FILL_BLOCKS, 256>>>(ei, w);
    k_gemm    <<<dim3((N_NODES + 63) / 64, KK), 256, SMEM_DYN>>>(h, a_s, a_t);
    k_agg     <<<(KK * N_USERC * 32) / 256, 256>>>();
    k_fusecls <<<N_USERC / 8, 256>>>(h, w1, w2, m, fcw, fcb, out);
}

// round 17
// speedup vs baseline: 2.7340x; 1.5394x over previous
#include <cuda_runtime.h>
#include <cstdint>

#define N_NODES 50000
#define N_USERC 40000
#define NE      400000
#define KK      3
#define NH      4
#define F_INC   128
#define F_OUTC  64
#define NC      40
#define SLOPE   0.2f
#define CAP     64

// ---------------- scratch (device globals; no allocations) ----------------
__device__ float g_hp [(size_t)KK * N_NODES * 256];   // 153.6 MB  [k][n][f*4+h]
__device__ float g_s  [KK * N_NODES * 4];
__device__ float g_t  [KK * N_NODES * 4];
__device__ float g_x  [KK * N_USERC * 64];            // TA, flat rows r = k*N_USERC+n
__device__ float g_F  [N_USERC * 64];                 // feature @ w1
__device__ float g_P  [KK * N_USERC * 64];            // TA @ w2 (flat rows like g_x)
__device__ float g_fus[N_USERC * 64];
__device__ int   g_cnt[KK * N_USERC];                 // zero at rest: agg re-zeroes after read
__device__ int   g_adj[(size_t)KK * N_USERC * CAP];
// prearranged m16n8k8 tf32 B-fragments (L2-resident broadcast)
__device__ uint2 g_bfrag [KK * 16384];                // main gemm B
__device__ uint2 g_w1frag[16 * 8 * 32];               // w1: 16 ksteps x 8 ntiles
__device__ uint2 g_w2frag[8 * 8 * 32];                // w2: 8 ksteps x 8 ntiles
__device__ uint2 g_fcfrag[32 * 5 * 32];               // fc_w: 32 ksteps x 5 ntiles

__device__ __forceinline__ uint32_t f2tf32(float f) {
    uint32_t r;
    asm("cvt.rna.tf32.f32 %0, %1;" : "=r"(r) : "f"(f));
    return r;
}

__device__ __forceinline__ void mma_tf32(float* d, const uint32_t* a, uint2 b) {
    asm volatile(
        "mma.sync.aligned.m16n8k8.row.col.f32.tf32.tf32.f32 "
        "{%0,%1,%2,%3}, {%4,%5,%6,%7}, {%8,%9}, {%0,%1,%2,%3};\n"
        : "+f"(d[0]), "+f"(d[1]), "+f"(d[2]), "+f"(d[3])
        : "r"(a[0]), "r"(a[1]), "r"(a[2]), "r"(a[3]), "r"(b.x), "r"(b.y));
}

// ---------------- merged: adjacency fill + all B fragment preps ----------------
#define NB_B   (KK * 16384)                 // 49152
#define NB_W1  (16 * 8 * 32)                // 4096
#define NB_W2  (8 * 8 * 32)                 // 2048
#define NB_FC  (32 * 5 * 32)                // 5120
#define PREP_TOTAL (NB_B + NB_W1 + NB_W2 + NB_FC)    // 60416 (=236*256 exactly)
#define PREP_BLOCKS ((PREP_TOTAL + 255) / 256)
#define FILL_BLOCKS ((KK * NE + 255) / 256)

__global__ void k_fillprep(const int* __restrict__ ei, const float* __restrict__ w,
                           const float* __restrict__ w1, const float* __restrict__ w2,
                           const float* __restrict__ fcw) {
    int b = blockIdx.x;
    if (b < PREP_BLOCKS) {
        int id = b * 256 + threadIdx.x;
        if (id < NB_B) {
            int kk   = id / 16384;
            int r    = id - kk * 16384;
            int lane = r & 31;
            int nt   = (r >> 5) & 15;
            int ks   = (r >> 9) & 15;
            int ch   = r >> 13;
            int d0   = ks * 8 + (lane & 3);
            int c    = ch * 128 + nt * 8 + (lane >> 2);
            int f    = c >> 2, hh = c & 3;
            const float* wk = w + (size_t)kk * NH * F_INC * F_OUTC;
            uint2 bb;
            bb.x = f2tf32(wk[((size_t)hh * F_INC + d0) * F_OUTC + f]);
            bb.y = f2tf32(wk[((size_t)hh * F_INC + d0 + 4) * F_OUTC + f]);
            g_bfrag[id] = bb;
        } else if (id < NB_B + NB_W1) {
            int r = id - NB_B;
            int lane = r & 31, nt = (r >> 5) & 7, ks = r >> 8;
            int d0 = ks * 8 + (lane & 3), c = nt * 8 + (lane >> 2);
            uint2 bb;
            bb.x = f2tf32(w1[d0 * F_OUTC + c]);
            bb.y = f2tf32(w1[(d0 + 4) * F_OUTC + c]);
            g_w1frag[r] = bb;
        } else if (id < NB_B + NB_W1 + NB_W2) {
            int r = id - NB_B - NB_W1;
            int lane = r & 31, nt = (r >> 5) & 7, ks = r >> 8;
            int d0 = ks * 8 + (lane & 3), c = nt * 8 + (lane >> 2);
            uint2 bb;
            bb.x = f2tf32(w2[d0 * F_OUTC + c]);
            bb.y = f2tf32(w2[(d0 + 4) * F_OUTC + c]);
            g_w2frag[r] = bb;
        } else {
            int r = id - NB_B - NB_W1 - NB_W2;
            int lane = r & 31;
            int q = r >> 5;
            int nt = q % 5, ks = q / 5;
            int d0 = ks * 8 + (lane & 3), c = nt * 8 + (lane >> 2);
            uint2 bb;
            bb.x = f2tf32(fcw[d0 * NC + c]);
            bb.y = f2tf32(fcw[(d0 + 4) * NC + c]);
            g_fcfrag[r] = bb;
        }
    } else {
        int idx = (b - PREP_BLOCKS) * 256 + threadIdx.x;
        if (idx >= KK * NE) return;
        int k = idx / NE;
        int e = idx - k * NE;
        int trg = ei[(k * 2 + 1) * NE + e];
        if (trg >= N_USERC) return;
        int src = ei[(k * 2) * NE + e];
        int slot = k * N_USERC + trg;
        int pos = atomicAdd(&g_cnt[slot], 1);
        if (pos < CAP) g_adj[(size_t)slot * CAP + pos] = src;
    }
}

// ================= main tcgen tf32 GEMM: hp = h @ w[k] + fused s,t (R15 WIN, unchanged) ===
#define A_PAD   132
#define A_BYTES (64 * A_PAD * 4)         // 33792
#define SMEM_DYN (A_BYTES + 6144)

__global__ __launch_bounds__(256, 2)
void k_gemm(const float* __restrict__ h, const float* __restrict__ a_src,
            const float* __restrict__ a_trg) {
    extern __shared__ __align__(16) char base[];
    float* Asm    = (float*)base;
    float* s_asr  = (float*)(base + A_BYTES);
    float* s_atr  = s_asr + 256;
    float* sred_s = s_atr + 256;
    float* sred_t = sred_s + 512;

    const int k    = blockIdx.y;
    const int n0   = blockIdx.x * 64;
    const int tid  = threadIdx.x;
    const int wid  = tid >> 5;
    const int lane = tid & 31;
    const int rt   = wid & 3;
    const int ch   = wid >> 2;
    const int g    = lane >> 2;
    const int c    = lane & 3;

    if (tid < 256) {
        s_asr[tid] = a_src[k * 256 + (tid & 3) * 64 + (tid >> 2)];
        s_atr[tid] = a_trg[k * 256 + (tid & 3) * 64 + (tid >> 2)];
    }

    for (int idx = tid; idx < 64 * 32; idx += 256) {
        int row = idx >> 5;
        int c4  = idx & 31;
        int n   = n0 + row;
        float4 av = make_float4(0.f, 0.f, 0.f, 0.f);
        if (n < N_NODES) av = *(const float4*)(h + (size_t)n * F_INC + c4 * 4);
        uint4 tv;
        tv.x = f2tf32(av.x); tv.y = f2tf32(av.y); tv.z = f2tf32(av.z); tv.w = f2tf32(av.w);
        *(uint4*)(Asm + row * A_PAD + c4 * 4) = tv;
    }
    __syncthreads();

    float acc[16][4];
#pragma unroll
    for (int nt = 0; nt < 16; nt++)
#pragma unroll
        for (int j = 0; j < 4; j++) acc[nt][j] = 0.f;

    const float* arow = Asm + (rt * 16 + g) * A_PAD;
    const uint2* bwarp = g_bfrag + (size_t)k * 16384 + (ch * 16) * 16 * 32 + lane;
#pragma unroll 2
    for (int ks = 0; ks < 16; ks++) {
        int col = ks * 8 + c;
        uint32_t a[4];
        a[0] = __float_as_uint(arow[col]);
        a[1] = __float_as_uint(arow[8 * A_PAD + col]);
        a[2] = __float_as_uint(arow[col + 4]);
        a[3] = __float_as_uint(arow[8 * A_PAD + col + 4]);
        const uint2* bk = bwarp + (size_t)ks * 16 * 32;
        uint2 b[16];
#pragma unroll
        for (int nt = 0; nt < 16; nt++) b[nt] = bk[nt * 32];
#pragma unroll
        for (int nt = 0; nt < 16; nt++)
            mma_tf32(acc[nt], a, b[nt]);
    }

    int nrow0 = n0 + rt * 16 + g;
    int nrow1 = nrow0 + 8;
    float sp00 = 0.f, sp01 = 0.f, sp10 = 0.f, sp11 = 0.f;
    float tp00 = 0.f, tp01 = 0.f, tp10 = 0.f, tp11 = 0.f;
    float* hp0 = g_hp + ((size_t)k * N_NODES + nrow0) * 256;
    float* hp1 = g_hp + ((size_t)k * N_NODES + nrow1) * 256;
    bool ok0 = (nrow0 < N_NODES), ok1 = (nrow1 < N_NODES);
#pragma unroll
    for (int nt = 0; nt < 16; nt++) {
        int cb = ch * 128 + nt * 8 + 2 * c;
        float w0 = s_asr[cb], w1v = s_asr[cb + 1];
        float v0 = s_atr[cb], v1 = s_atr[cb + 1];
        sp00 += acc[nt][0] * w0; sp01 += acc[nt][1] * w1v;
        sp10 += acc[nt][2] * w0; sp11 += acc[nt][3] * w1v;
        tp00 += acc[nt][0] * v0; tp01 += acc[nt][1] * v1;
        tp10 += acc[nt][2] * v0; tp11 += acc[nt][3] * v1;
        if (ok0) *(float2*)(hp0 + cb) = make_float2(acc[nt][0], acc[nt][1]);
        if (ok1) *(float2*)(hp1 + cb) = make_float2(acc[nt][2], acc[nt][3]);
    }
    sp00 += __shfl_xor_sync(0xffffffffu, sp00, 2);
    sp01 += __shfl_xor_sync(0xffffffffu, sp01, 2);
    sp10 += __shfl_xor_sync(0xffffffffu, sp10, 2);
    sp11 += __shfl_xor_sync(0xffffffffu, sp11, 2);
    tp00 += __shfl_xor_sync(0xffffffffu, tp00, 2);
    tp01 += __shfl_xor_sync(0xffffffffu, tp01, 2);
    tp10 += __shfl_xor_sync(0xffffffffu, tp10, 2);
    tp11 += __shfl_xor_sync(0xffffffffu, tp11, 2);
    if (c < 2) {
        int b0 = ((wid * 8 + g) * 2 + 0) * 4 + 2 * c;
        int b1 = ((wid * 8 + g) * 2 + 1) * 4 + 2 * c;
        sred_s[b0] = sp00; sred_s[b0 + 1] = sp01;
        sred_s[b1] = sp10; sred_s[b1 + 1] = sp11;
        sred_t[b0] = tp00; sred_t[b0 + 1] = tp01;
        sred_t[b1] = tp10; sred_t[b1 + 1] = tp11;
    }
    __syncthreads();
    {
        int row = tid >> 2, hh = tid & 3;
        int n = n0 + row;
        if (n < N_NODES) {
            int rtf = row >> 4, rr = row & 15, gg = rr & 7, r = rr >> 3;
            int i0 = ((rtf * 8 + gg) * 2 + r) * 4 + hh;
            int i1 = (((rtf + 4) * 8 + gg) * 2 + r) * 4 + hh;
            size_t o = ((size_t)k * N_NODES + n) * 4 + hh;
            g_s[o] = sred_s[i0] + sred_s[i1];
            g_t[o] = sred_t[i0] + sred_t[i1];
        }
    }
}

// ================= k_gemmF: F = h[:40000] @ w1 (tf32 MMA) =================
__global__ __launch_bounds__(256) void k_gemmF(const float* __restrict__ h) {
    __shared__ float Asm[64 * A_PAD];
    const int n0   = blockIdx.x * 64;      // grid 625, exact
    const int tid  = threadIdx.x;
    const int wid  = tid >> 5;
    const int lane = tid & 31;
    const int rt   = wid & 3;
    const int ch   = wid >> 2;
    const int g    = lane >> 2;
    const int c    = lane & 3;

    for (int idx = tid; idx < 64 * 32; idx += 256) {
        int row = idx >> 5;
        int c4  = idx & 31;
        float4 av = *(const float4*)(h + (size_t)(n0 + row) * F_INC + c4 * 4);
        uint4 tv;
        tv.x = f2tf32(av.x); tv.y = f2tf32(av.y); tv.z = f2tf32(av.z); tv.w = f2tf32(av.w);
        *(uint4*)(Asm + row * A_PAD + c4 * 4) = tv;
    }
    __syncthreads();

    float acc[4][4];
#pragma unroll
    for (int nt = 0; nt < 4; nt++)
#pragma unroll
        for (int j = 0; j < 4; j++) acc[nt][j] = 0.f;

    const float* arow = Asm + (rt * 16 + g) * A_PAD;
#pragma unroll 4
    for (int ks = 0; ks < 16; ks++) {
        int col = ks * 8 + c;
        uint32_t a[4];
        a[0] = __float_as_uint(arow[col]);
        a[1] = __float_as_uint(arow[8 * A_PAD + col]);
        a[2] = __float_as_uint(arow[col + 4]);
        a[3] = __float_as_uint(arow[8 * A_PAD + col + 4]);
#pragma unroll
        for (int nt = 0; nt < 4; nt++)
            mma_tf32(acc[nt], a, g_w1frag[(ks * 8 + ch * 4 + nt) * 32 + lane]);
    }
    int nrow0 = n0 + rt * 16 + g;
#pragma unroll
    for (int nt = 0; nt < 4; nt++) {
        int cb = ch * 32 + nt * 8 + 2 * c;
        *(float2*)(g_F + (size_t)nrow0 * 64 + cb)       = make_float2(acc[nt][0], acc[nt][1]);
        *(float2*)(g_F + (size_t)(nrow0 + 8) * 64 + cb) = make_float2(acc[nt][2], acc[nt][3]);
    }
}

// ================= k_gemmP: P = g_x_flat[120000x64] @ w2 (tf32 MMA) =================
#define AP_PAD 68
__global__ __launch_bounds__(256) void k_gemmP() {
    __shared__ float Asm[64 * AP_PAD];
    const int r0   = blockIdx.x * 64;      // grid 1875, exact
    const int tid  = threadIdx.x;
    const int wid  = tid >> 5;
    const int lane = tid & 31;
    const int rt   = wid & 3;
    const int ch   = wid >> 2;
    const int g    = lane >> 2;
    const int c    = lane & 3;

    for (int idx = tid; idx < 64 * 16; idx += 256) {
        int row = idx >> 4;
        int c4  = idx & 15;
        float4 av = *(const float4*)(g_x + (size_t)(r0 + row) * 64 + c4 * 4);
        uint4 tv;
        tv.x = f2tf32(av.x); tv.y = f2tf32(av.y); tv.z = f2tf32(av.z); tv.w = f2tf32(av.w);
        *(uint4*)(Asm + row * AP_PAD + c4 * 4) = tv;
    }
    __syncthreads();

    float acc[4][4];
#pragma unroll
    for (int nt = 0; nt < 4; nt++)
#pragma unroll
        for (int j = 0; j < 4; j++) acc[nt][j] = 0.f;

    const float* arow = Asm + (rt * 16 + g) * AP_PAD;
#pragma unroll
    for (int ks = 0; ks < 8; ks++) {
        int col = ks * 8 + c;
        uint32_t a[4];
        a[0] = __float_as_uint(arow[col]);
        a[1] = __float_as_uint(arow[8 * AP_PAD + col]);
        a[2] = __float_as_uint(arow[col + 4]);
        a[3] = __float_as_uint(arow[8 * AP_PAD + col + 4]);
#pragma unroll
        for (int nt = 0; nt < 4; nt++)
            mma_tf32(acc[nt], a, g_w2frag[(ks * 8 + ch * 4 + nt) * 32 + lane]);
    }
    int r = r0 + rt * 16 + g;
#pragma unroll
    for (int nt = 0; nt < 4; nt++) {
        int cb = ch * 32 + nt * 8 + 2 * c;
        *(float2*)(g_P + (size_t)r * 64 + cb)       = make_float2(acc[nt][0], acc[nt][1]);
        *(float2*)(g_P + (size_t)(r + 8) * 64 + cb) = make_float2(acc[nt][2], acc[nt][3]);
    }
}

__device__ __forceinline__ float lrelu_exp(float v) {
    v = (v >= 0.f) ? v : SLOPE * v;
    return __expf(v);
}

// ---------------- fused softmax + aggregation (warp per (k,trg)) — unchanged ----------------
__global__ __launch_bounds__(256) void k_agg() {
    int gw   = (blockIdx.x * blockDim.x + threadIdx.x) >> 5;
    int lane = threadIdx.x & 31;
    if (gw >= KK * N_USERC) return;
    int k = gw / N_USERC;
    int n = gw - k * N_USERC;
    float* xr = g_x + (size_t)gw * 64;

    int deg = g_cnt[gw];
    if (lane == 0 && deg != 0) g_cnt[gw] = 0;
    deg = (deg > CAP) ? CAP : deg;
    if (deg == 0) {
        xr[lane] = 0.f;
        xr[lane + 32] = 0.f;
        return;
    }
    float4 tv = *(const float4*)(g_t + ((size_t)k * N_NODES + n) * 4);
    const int* adj = g_adj + (size_t)gw * CAP;

    int src0 = (lane < deg)      ? adj[lane]      : 0;
    int src1 = (lane + 32 < deg) ? adj[lane + 32] : 0;
    float4 ex0 = make_float4(0.f, 0.f, 0.f, 0.f);
    float4 ex1 = make_float4(0.f, 0.f, 0.f, 0.f);
    if (lane < deg) {
        float4 sv = *(const float4*)(g_s + ((size_t)k * N_NODES + src0) * 4);
        ex0.x = lrelu_exp(sv.x + tv.x); ex0.y = lrelu_exp(sv.y + tv.y);
        ex0.z = lrelu_exp(sv.z + tv.z); ex0.w = lrelu_exp(sv.w + tv.w);
    }
    if (lane + 32 < deg) {
        float4 sv = *(const float4*)(g_s + ((size_t)k * N_NODES + src1) * 4);
        ex1.x = lrelu_exp(sv.x + tv.x); ex1.y = lrelu_exp(sv.y + tv.y);
        ex1.z = lrelu_exp(sv.z + tv.z); ex1.w = lrelu_exp(sv.w + tv.w);
    }
    float dx = ex0.x + ex1.x, dy = ex0.y + ex1.y, dz = ex0.z + ex1.z, dw = ex0.w + ex1.w;
#pragma unroll
    for (int off = 16; off; off >>= 1) {
        dx += __shfl_xor_sync(0xffffffffu, dx, off);
        dy += __shfl_xor_sync(0xffffffffu, dy, off);
        dz += __shfl_xor_sync(0xffffffffu, dz, off);
        dw += __shfl_xor_sync(0xffffffffu, dw, off);
    }
    float ix = 0.25f / (dx + 1e-16f);
    float iy = 0.25f / (dy + 1e-16f);
    float iz = 0.25f / (dz + 1e-16f);
    float iw = 0.25f / (dw + 1e-16f);

    const float4* hpb = ((const float4*)g_hp) + (size_t)k * N_NODES * 64;
    float m0 = 0.f, m1 = 0.f;
    int d0 = (deg < 32) ? deg : 32;
    for (int j = 0; j < d0; j++) {
        int   s  = __shfl_sync(0xffffffffu, src0, j);
        float ax = __shfl_sync(0xffffffffu, ex0.x, j) * ix;
        float ay = __shfl_sync(0xffffffffu, ex0.y, j) * iy;
        float az = __shfl_sync(0xffffffffu, ex0.z, j) * iz;
        float aw = __shfl_sync(0xffffffffu, ex0.w, j) * iw;
        const float4* hp4 = hpb + (size_t)s * 64;
        float4 h0 = hp4[lane];
        float4 h1 = hp4[lane + 32];
        m0 += h0.x * ax + h0.y * ay + h0.z * az + h0.w * aw;
        m1 += h1.x * ax + h1.y * ay + h1.z * az + h1.w * aw;
    }
    for (int j = 32; j < deg; j++) {
        int   s  = __shfl_sync(0xffffffffu, src1, j - 32);
        float ax = __shfl_sync(0xffffffffu, ex1.x, j - 32) * ix;
        float ay = __shfl_sync(0xffffffffu, ex1.y, j - 32) * iy;
        float az = __shfl_sync(0xffffffffu, ex1.z, j - 32) * iz;
        float aw = __shfl_sync(0xffffffffu, ex1.w, j - 32) * iw;
        const float4* hp4 = hpb + (size_t)s * 64;
        float4 h0 = hp4[lane];
        float4 h1 = hp4[lane + 32];
        m0 += h0.x * ax + h0.y * ay + h0.z * az + h0.w * aw;
        m1 += h1.x * ax + h1.y * ay + h1.z * az + h1.w * aw;
    }
    xr[lane]      = m0;
    xr[lane + 32] = m1;
}

// ---------------- k_fuse2: semantic attention glue (warp/node, pure float4 loads) ----------
__global__ __launch_bounds__(256) void k_fuse2(const float* __restrict__ m) {
    int n    = blockIdx.x * 8 + (threadIdx.x >> 5);   // 5000 blocks, exact
    int lane = threadIdx.x & 31;
    float F0 = g_F[(size_t)n * 64 + lane];
    float F1 = g_F[(size_t)n * 64 + lane + 32];
    float ml = __ldg(m + lane), mh = __ldg(m + lane + 32);
    float ta0[KK], ta1[KK], sc[KK];
#pragma unroll
    for (int k = 0; k < KK; k++) {
        size_t r = (size_t)(k * N_USERC + n) * 64;
        float t0 = g_x[r + lane], t1 = g_x[r + lane + 32];
        float P0 = g_P[r + lane], P1 = g_P[r + lane + 32];
        ta0[k] = t0; ta1[k] = t1;
        float q0 = tanhf(F0 + P0);
        float q1 = tanhf(F1 + P1);
        float s = q0 * ml + q1 * mh;
#pragma unroll
        for (int off = 16; off; off >>= 1) s += __shfl_xor_sync(0xffffffffu, s, off);
        sc[k] = s;
    }
    float mx = fmaxf(sc[0], fmaxf(sc[1], sc[2]));
    float e0 = __expf(sc[0] - mx), e1 = __expf(sc[1] - mx), e2 = __expf(sc[2] - mx);
    float inv = 1.f / (e0 + e1 + e2);
    float b0 = e0 * inv, b1 = e1 * inv, b2 = e2 * inv;
    g_fus[(size_t)n * 64 + lane]      = b0 * ta0[0] + b1 * ta0[1] + b2 * ta0[2];
    g_fus[(size_t)n * 64 + lane + 32] = b0 * ta1[0] + b1 * ta1[1] + b2 * ta1[2];
}

// ================= k_gemmC: logits = [TA0|TA1|TA2|fus] @ fc_w, fused log_softmax =========
#define AC_PAD 260
#define AC_BYTES (64 * AC_PAD * 4)     // 66560
__global__ __launch_bounds__(128) void k_gemmC(const float* __restrict__ fcb,
                                               float* __restrict__ out) {
    extern __shared__ __align__(16) float Asm2[];
    const int n0   = blockIdx.x * 64;     // grid 625, exact
    const int tid  = threadIdx.x;
    const int wid  = tid >> 5;            // 0..3 = row tile
    const int lane = tid & 31;
    const int g    = lane >> 2;
    const int c    = lane & 3;

    // stage A: 64 rows x 256 cols (3x TA + fusion), fp32 -> tf32
    for (int idx = tid; idx < 64 * 64; idx += 128) {
        int row = idx >> 6;
        int c4  = idx & 63;
        int src = c4 >> 4;                // 0..3
        int c4l = c4 & 15;
        float4 v;
        if (src < 3) v = *(const float4*)(g_x + ((size_t)(src * N_USERC) + n0 + row) * 64 + c4l * 4);
        else         v = *(const float4*)(g_fus + (size_t)(n0 + row) * 64 + c4l * 4);
        uint4 tv;
        tv.x = f2tf32(v.x); tv.y = f2tf32(v.y); tv.z = f2tf32(v.z); tv.w = f2tf32(v.w);
        *(uint4*)(Asm2 + row * AC_PAD + c4 * 4) = tv;
    }
    __syncthreads();

    float acc[5][4];
#pragma unroll
    for (int nt = 0; nt < 5; nt++)
#pragma unroll
        for (int j = 0; j < 4; j++) acc[nt][j] = 0.f;

    const float* arow = Asm2 + (wid * 16 + g) * AC_PAD;
#pragma unroll 4
    for (int ks = 0; ks < 32; ks++) {
        int col = ks * 8 + c;
        uint32_t a[4];
        a[0] = __float_as_uint(arow[col]);
        a[1] = __float_as_uint(arow[8 * AC_PAD + col]);
        a[2] = __float_as_uint(arow[col + 4]);
        a[3] = __float_as_uint(arow[8 * AC_PAD + col + 4]);
#pragma unroll
        for (int nt = 0; nt < 5; nt++)
            mma_tf32(acc[nt], a, g_fcfrag[(ks * 5 + nt) * 32 + lane]);
    }

    // bias + fused log_softmax on fragments: rows g and g+8 within this warp's 16-row tile
    float l0[5][2], l1[5][2];
    float vm0 = -1e30f, vm1 = -1e30f;
#pragma unroll
    for (int nt = 0; nt < 5; nt++) {
        float bb0 = __ldg(fcb + nt * 8 + 2 * c);
        float bb1 = __ldg(fcb + nt * 8 + 2 * c + 1);
        l0[nt][0] = acc[nt][0] + bb0; l0[nt][1] = acc[nt][1] + bb1;
        l1[nt][0] = acc[nt][2] + bb0; l1[nt][1] = acc[nt][3] + bb1;
        vm0 = fmaxf(vm0, fmaxf(l0[nt][0], l0[nt][1]));
        vm1 = fmaxf(vm1, fmaxf(l1[nt][0], l1[nt][1]));
    }
    // reduce across the 4 lanes sharing a row (lane = g*4 + c; xor 1,2 stay in group)
    vm0 = fmaxf(vm0, __shfl_xor_sync(0xffffffffu, vm0, 1));
    vm0 = fmaxf(vm0, __shfl_xor_sync(0xffffffffu, vm0, 2));
    vm1 = fmaxf(vm1, __shfl_xor_sync(0xffffffffu, vm1, 1));
    vm1 = fmaxf(vm1, __shfl_xor_sync(0xffffffffu, vm1, 2));
    float se0 = 0.f, se1 = 0.f;
#pragma unroll
    for (int nt = 0; nt < 5; nt++) {
        se0 += expf(l0[nt][0] - vm0) + expf(l0[nt][1] - vm0);
        se1 += expf(l1[nt][0] - vm1) + expf(l1[nt][1] - vm1);
    }
    se0 += __shfl_xor_sync(0xffffffffu, se0, 1);
    se0 += __shfl_xor_sync(0xffffffffu, se0, 2);
    se1 += __shfl_xor_sync(0xffffffffu, se1, 1);
    se1 += __shfl_xor_sync(0xffffffffu, se1, 2);
    float ls0 = vm0 + logf(se0);
    float ls1 = vm1 + logf(se1);

    int nrow0 = n0 + wid * 16 + g;
    int nrow1 = nrow0 + 8;
#pragma unroll
    for (int nt = 0; nt < 5; nt++) {
        int cb = nt * 8 + 2 * c;
        *(float2*)(out + (size_t)nrow0 * NC + cb) = make_float2(l0[nt][0] - ls0, l0[nt][1] - ls0);
        *(float2*)(out + (size_t)nrow1 * NC + cb) = make_float2(l1[nt][0] - ls1, l1[nt][1] - ls1);
    }
}

// ---------------- launch ----------------
extern "C" void kernel_launch(void* const* d_in, const int* in_sizes, int n_in,
                              void* d_out, int out_size) {
    (void)in_sizes; (void)n_in; (void)out_size;
    const float* h   = (const float*)d_in[0];
    const int*   ei  = (const int*)d_in[1];
    const float* w   = (const float*)d_in[2];
    const float* a_s = (const float*)d_in[3];
    const float* a_t = (const float*)d_in[4];
    const float* w1  = (const float*)d_in[5];
    const float* w2  = (const float*)d_in[6];
    const float* m   = (const float*)d_in[7];
    const float* fcw = (const float*)d_in[8];
    const float* fcb = (const float*)d_in[9];
    float* out = (float*)d_out;

    cudaFuncSetAttribute(k_gemm,  cudaFuncAttributeMaxDynamicSharedMemorySize, SMEM_DYN);
    cudaFuncSetAttribute(k_gemmC, cudaFuncAttributeMaxDynamicSharedMemorySize, AC_BYTES);

    k_fillprep<<<PREP_BLOCKS + FILL_BLOCKS, 256>>>(ei, w, w1, w2, fcw);
    k_gemm    <<<dim3((N_NODES + 63) / 64, KK), 256, SMEM_DYN>>>(h, a_s, a_t);
    k_gemmF   <<<N_USERC / 64, 256>>>(h);
    k_agg     <<<(KK * N_USERC * 32) / 256, 256>>>();      // 4th launch = ncu capture
    k_gemmP   <<<(KK * N_USERC) / 64, 256>>>();
    k_fuse2   <<<N_USERC / 8, 256>>>(m);
    k_gemmC   <<<N_USERC / 64, 128, AC_BYTES>>>(fcb, out);
}